// round 15
// baseline (speedup 1.0000x reference)
#include <cuda_runtime.h>
#include <cuda_bf16.h>
#include <cstdint>

#define N_USERS 30000
#define N_ITEMS 30000
#define N_NODES 60000
#define D 64
#define IMG_DIM 2048
#define TXT_DIM 384
#define NNZ_NORM 2000000
#define NNZ_ADJ  1000000
#define NNZ_G    150000
#define NNZ_TOT  3900000

#define SEG_NORM   0
#define SEG_ADJ    2000000
#define SEG_IMG_II 3000000
#define SEG_TXT_II 3150000
#define SEG_IMG_UU 3300000
#define SEG_TXT_UU 3450000
#define SEG_CII    3600000
#define SEG_CUU    3750000

#define RPO_NORM   0
#define RPO_ADJ    60001
#define RPO_IMG_II 90002
#define RPO_TXT_II 120003
#define RPO_IMG_UU 150004
#define RPO_TXT_UU 180005
#define RPO_CII    210006
#define RPO_CUU    240007
#define RP_TOTAL   270008

// ---------------- scratch ----------------
__device__ float g_egoA[N_NODES * D];
__device__ float g_egoB[N_NODES * D];
__device__ float g_cge [N_NODES * D];

__device__ float g_fv   [N_ITEMS * D];
__device__ float g_comv [N_ITEMS * D];
__device__ float g_persv[N_ITEMS * D];
__device__ float g_ft   [N_ITEMS * D];
__device__ float g_comt [N_ITEMS * D];
__device__ float g_perst[N_ITEMS * D];

__device__ float g_upv[N_USERS * D];
__device__ float g_ucv[N_USERS * D];
__device__ float g_upt[N_USERS * D];
__device__ float g_uct[N_USERS * D];

__device__ float g_pev[N_NODES * D];
__device__ float g_cev[N_NODES * D];
__device__ float g_pet[N_NODES * D];
__device__ float g_cet[N_NODES * D];

__device__ int   g_counts[RP_TOTAL];
__device__ int   g_rowptr[RP_TOTAL];
__device__ int   g_cursor[RP_TOTAL];
__device__ int   g_colss [NNZ_TOT];
__device__ float g_valss [NNZ_TOT];

__constant__ int c_nrows[8] = {60000,30000,30000,30000,30000,30000,30000,30000};
__constant__ int c_rpoff[8] = {RPO_NORM,RPO_ADJ,RPO_IMG_II,RPO_TXT_II,RPO_IMG_UU,RPO_TXT_UU,RPO_CII,RPO_CUU};

// ---------------- helpers ----------------
__device__ __forceinline__ float sigmoidf_(float x) {
    return 1.0f / (1.0f + __expf(-x));
}
__device__ __forceinline__ unsigned long long fma2_(unsigned long long a, unsigned long long b,
                                                    unsigned long long c) {
    unsigned long long d;
    asm("fma.rn.f32x2 %0, %1, %2, %3;" : "=l"(d) : "l"(a), "l"(b), "l"(c));
    return d;
}
__device__ __forceinline__ unsigned long long pack2_(float lo, float hi) {
    unsigned long long d;
    asm("mov.b64 %0, {%1, %2};" : "=l"(d) : "f"(lo), "f"(hi));
    return d;
}
__device__ __forceinline__ float2 unpack2_(unsigned long long v) {
    float2 r;
    asm("mov.b64 {%0, %1}, %2;" : "=f"(r.x), "=f"(r.y) : "l"(v));
    return r;
}
__device__ __forceinline__ void red_add_f(float* addr, float v) {
    asm volatile("red.global.add.f32 [%0], %1;" :: "l"(addr), "f"(v) : "memory");
}

// ---------------- CSR build ----------------
#define HIST_BLOCKS 15235   // ceil(NNZ_TOT/256)
#define CAT_BLOCKS  3750    // N_NODES*D/4/256

__global__ void build1_kernel(const int* __restrict__ i0, const int* __restrict__ i1,
                              const int* __restrict__ i2, const int* __restrict__ i3,
                              const int* __restrict__ i4, const int* __restrict__ i5,
                              const int* __restrict__ i6, const int* __restrict__ i7,
                              int* __restrict__ counts,
                              const float* __restrict__ u, const float* __restrict__ it,
                              float* __restrict__ ego) {
    if (blockIdx.x < HIST_BLOCKS) {
        int gid = blockIdx.x * 256 + threadIdx.x;
        if (gid >= NNZ_TOT) return;
        const int* rows; int i, rpo;
        if      (gid < SEG_ADJ)    { rows = i0; i = gid - SEG_NORM;   rpo = RPO_NORM;   }
        else if (gid < SEG_IMG_II) { rows = i1; i = gid - SEG_ADJ;    rpo = RPO_ADJ;    }
        else if (gid < SEG_TXT_II) { rows = i2; i = gid - SEG_IMG_II; rpo = RPO_IMG_II; }
        else if (gid < SEG_IMG_UU) { rows = i3; i = gid - SEG_TXT_II; rpo = RPO_TXT_II; }
        else if (gid < SEG_TXT_UU) { rows = i4; i = gid - SEG_IMG_UU; rpo = RPO_IMG_UU; }
        else if (gid < SEG_CII)    { rows = i5; i = gid - SEG_TXT_UU; rpo = RPO_TXT_UU; }
        else if (gid < SEG_CUU)    { rows = i6; i = gid - SEG_CII;    rpo = RPO_CII;    }
        else                       { rows = i7; i = gid - SEG_CUU;    rpo = RPO_CUU;    }
        atomicAdd(&counts[rpo + __ldg(rows + i)], 1);
    } else {
        int i = (blockIdx.x - HIST_BLOCKS) * 256 + threadIdx.x;
        int n_half4 = (N_USERS * D) / 4;
        int n_tot4  = (N_NODES * D) / 4;
        if (i >= n_tot4) return;
        const float4* src = (i < n_half4) ? (const float4*)u : (const float4*)it;
        int j = (i < n_half4) ? i : (i - n_half4);
        ((float4*)ego)[i] = src[j];
    }
}

__global__ void scan_kernel(const int* __restrict__ counts, int* __restrict__ rowptr) {
    int m = blockIdx.x;
    int n = c_nrows[m];
    const int* cnt = counts + c_rpoff[m];
    int* rp = rowptr + c_rpoff[m];
    __shared__ int part[1024];
    int tid = threadIdx.x;
    int chunk = (n + 1023) >> 10;
    int lo = tid * chunk;
    int hi = lo + chunk; if (hi > n) hi = n;
    int s = 0;
    for (int i = lo; i < hi; i++) s += cnt[i];
    part[tid] = s;
    __syncthreads();
    for (int off = 1; off < 1024; off <<= 1) {
        int v = (tid >= off) ? part[tid - off] : 0;
        __syncthreads();
        part[tid] += v;
        __syncthreads();
    }
    int base = (tid == 0) ? 0 : part[tid - 1];
    for (int i = lo; i < hi; i++) { rp[i] = base; base += cnt[i]; }
    if (lo < n && hi == n) rp[n] = base;
}

// scatter over gid range [gid0, gid0+gcount)
__global__ void scatter_kernel(const int* __restrict__ i0, const int* __restrict__ i1,
                               const int* __restrict__ i2, const int* __restrict__ i3,
                               const int* __restrict__ i4, const int* __restrict__ i5,
                               const int* __restrict__ i6, const int* __restrict__ i7,
                               const float* __restrict__ v0, const float* __restrict__ v1,
                               const float* __restrict__ v2, const float* __restrict__ v3,
                               const float* __restrict__ v4, const float* __restrict__ v5,
                               const float* __restrict__ v6, const float* __restrict__ v7,
                               const float* __restrict__ num_inters,
                               int* __restrict__ cursor,
                               int* __restrict__ cols_s, float* __restrict__ vals_s,
                               int gid0, int gcount) {
    int gid = gid0 + blockIdx.x * blockDim.x + threadIdx.x;
    if (gid >= gid0 + gcount) return;
    const int* idx; const float* vls; int i, rpo, seg, nz; bool sc;
    if      (gid < SEG_ADJ)    { idx=i0; vls=v0; i=gid-SEG_NORM;   rpo=RPO_NORM;   seg=SEG_NORM;   nz=NNZ_NORM; sc=false; }
    else if (gid < SEG_IMG_II) { idx=i1; vls=v1; i=gid-SEG_ADJ;    rpo=RPO_ADJ;    seg=SEG_ADJ;    nz=NNZ_ADJ;  sc=false; }
    else if (gid < SEG_TXT_II) { idx=i2; vls=v2; i=gid-SEG_IMG_II; rpo=RPO_IMG_II; seg=SEG_IMG_II; nz=NNZ_G;    sc=false; }
    else if (gid < SEG_IMG_UU) { idx=i3; vls=v3; i=gid-SEG_TXT_II; rpo=RPO_TXT_II; seg=SEG_TXT_II; nz=NNZ_G;    sc=false; }
    else if (gid < SEG_TXT_UU) { idx=i4; vls=v4; i=gid-SEG_IMG_UU; rpo=RPO_IMG_UU; seg=SEG_IMG_UU; nz=NNZ_G;    sc=true;  }
    else if (gid < SEG_CII)    { idx=i5; vls=v5; i=gid-SEG_TXT_UU; rpo=RPO_TXT_UU; seg=SEG_TXT_UU; nz=NNZ_G;    sc=true;  }
    else if (gid < SEG_CUU)    { idx=i6; vls=v6; i=gid-SEG_CII;    rpo=RPO_CII;    seg=SEG_CII;    nz=NNZ_G;    sc=false; }
    else                       { idx=i7; vls=v7; i=gid-SEG_CUU;    rpo=RPO_CUU;    seg=SEG_CUU;    nz=NNZ_G;    sc=true;  }
    int r = __ldg(idx + i);
    int c = __ldg(idx + nz + i);
    float v = __ldg(vls + i);
    if (sc) v *= __ldg(num_inters + c);
    int pos = atomicAdd(&cursor[rpo + r], 1);
    cols_s[seg + pos] = c;
    vals_s[seg + pos] = v;
}

// ---------------- SpMM device building blocks ----------------

__device__ __forceinline__ void spmm1_device(const int* __restrict__ rowptr,
                                             const int* __restrict__ cols,
                                             const float* __restrict__ vals,
                                             const float* __restrict__ x,
                                             float* __restrict__ o,
                                             float* __restrict__ cge,
                                             int mode, int n_rows, int row_off, int blk) {
    int t = blk * 256 + threadIdx.x;
    int row = t >> 4, lane = t & 15;
    if (row >= n_rows) return;
    int start = __ldg(rowptr + row), end = __ldg(rowptr + row + 1);
    float4 a0 = make_float4(0.f,0.f,0.f,0.f);
    float4 a1 = make_float4(0.f,0.f,0.f,0.f);
    float4 a2 = make_float4(0.f,0.f,0.f,0.f);
    float4 a3 = make_float4(0.f,0.f,0.f,0.f);
    int k = start;
    for (; k + 4 <= end; k += 4) {
        int   c0 = __ldg(cols + k), c1 = __ldg(cols + k + 1);
        int   c2 = __ldg(cols + k + 2), c3 = __ldg(cols + k + 3);
        float w0 = __ldg(vals + k), w1 = __ldg(vals + k + 1);
        float w2 = __ldg(vals + k + 2), w3 = __ldg(vals + k + 3);
        float4 p0 = __ldg((const float4*)(x + (size_t)c0 * D) + lane);
        float4 p1 = __ldg((const float4*)(x + (size_t)c1 * D) + lane);
        float4 p2 = __ldg((const float4*)(x + (size_t)c2 * D) + lane);
        float4 p3 = __ldg((const float4*)(x + (size_t)c3 * D) + lane);
        a0.x = fmaf(w0, p0.x, a0.x); a0.y = fmaf(w0, p0.y, a0.y);
        a0.z = fmaf(w0, p0.z, a0.z); a0.w = fmaf(w0, p0.w, a0.w);
        a1.x = fmaf(w1, p1.x, a1.x); a1.y = fmaf(w1, p1.y, a1.y);
        a1.z = fmaf(w1, p1.z, a1.z); a1.w = fmaf(w1, p1.w, a1.w);
        a2.x = fmaf(w2, p2.x, a2.x); a2.y = fmaf(w2, p2.y, a2.y);
        a2.z = fmaf(w2, p2.z, a2.z); a2.w = fmaf(w2, p2.w, a2.w);
        a3.x = fmaf(w3, p3.x, a3.x); a3.y = fmaf(w3, p3.y, a3.y);
        a3.z = fmaf(w3, p3.z, a3.z); a3.w = fmaf(w3, p3.w, a3.w);
    }
    for (; k < end; k++) {
        int   c0 = __ldg(cols + k);
        float w0 = __ldg(vals + k);
        float4 p0 = __ldg((const float4*)(x + (size_t)c0 * D) + lane);
        a0.x = fmaf(w0, p0.x, a0.x); a0.y = fmaf(w0, p0.y, a0.y);
        a0.z = fmaf(w0, p0.z, a0.z); a0.w = fmaf(w0, p0.w, a0.w);
    }
    a0.x += a1.x + a2.x + a3.x;
    a0.y += a1.y + a2.y + a3.y;
    a0.z += a1.z + a2.z + a3.z;
    a0.w += a1.w + a2.w + a3.w;
    size_t obase = (size_t)(row + row_off) * D;
    ((float4*)(o + obase))[lane] = a0;
    if (mode == 1) {
        ((float4*)(cge + obase))[lane] = a0;
    } else if (mode == 2) {
        float4 t4 = ((float4*)(cge + obase))[lane];
        t4.x += a0.x; t4.y += a0.y; t4.z += a0.z; t4.w += a0.w;
        ((float4*)(cge + obase))[lane] = t4;
    }
}

__device__ __forceinline__ void spmm2_device(const int* __restrict__ rowptr,
                                             const int* __restrict__ cols,
                                             const float* __restrict__ vals,
                                             const float* __restrict__ x0, const float* __restrict__ x1,
                                             float* __restrict__ o0, float* __restrict__ o1,
                                             int n_rows, int row_off, int blk) {
    int t = blk * 256 + threadIdx.x;
    int row = t >> 4, lane = t & 15;
    if (row >= n_rows) return;
    int start = __ldg(rowptr + row), end = __ldg(rowptr + row + 1);
    float4 a0 = make_float4(0.f,0.f,0.f,0.f);
    float4 a1 = make_float4(0.f,0.f,0.f,0.f);
    float4 b0 = make_float4(0.f,0.f,0.f,0.f);
    float4 b1 = make_float4(0.f,0.f,0.f,0.f);
    int k = start;
    for (; k + 2 <= end; k += 2) {
        int   c0 = __ldg(cols + k), c1 = __ldg(cols + k + 1);
        float w0 = __ldg(vals + k), w1 = __ldg(vals + k + 1);
        size_t f0 = (size_t)c0 * D, f1 = (size_t)c1 * D;
        float4 p00 = __ldg((const float4*)(x0 + f0) + lane);
        float4 p10 = __ldg((const float4*)(x1 + f0) + lane);
        float4 p01 = __ldg((const float4*)(x0 + f1) + lane);
        float4 p11 = __ldg((const float4*)(x1 + f1) + lane);
        a0.x = fmaf(w0, p00.x, a0.x); a0.y = fmaf(w0, p00.y, a0.y);
        a0.z = fmaf(w0, p00.z, a0.z); a0.w = fmaf(w0, p00.w, a0.w);
        b0.x = fmaf(w0, p10.x, b0.x); b0.y = fmaf(w0, p10.y, b0.y);
        b0.z = fmaf(w0, p10.z, b0.z); b0.w = fmaf(w0, p10.w, b0.w);
        a1.x = fmaf(w1, p01.x, a1.x); a1.y = fmaf(w1, p01.y, a1.y);
        a1.z = fmaf(w1, p01.z, a1.z); a1.w = fmaf(w1, p01.w, a1.w);
        b1.x = fmaf(w1, p11.x, b1.x); b1.y = fmaf(w1, p11.y, b1.y);
        b1.z = fmaf(w1, p11.z, b1.z); b1.w = fmaf(w1, p11.w, b1.w);
    }
    if (k < end) {
        int   c0 = __ldg(cols + k);
        float w0 = __ldg(vals + k);
        size_t f0 = (size_t)c0 * D;
        float4 p00 = __ldg((const float4*)(x0 + f0) + lane);
        float4 p10 = __ldg((const float4*)(x1 + f0) + lane);
        a0.x = fmaf(w0, p00.x, a0.x); a0.y = fmaf(w0, p00.y, a0.y);
        a0.z = fmaf(w0, p00.z, a0.z); a0.w = fmaf(w0, p00.w, a0.w);
        b0.x = fmaf(w0, p10.x, b0.x); b0.y = fmaf(w0, p10.y, b0.y);
        b0.z = fmaf(w0, p10.z, b0.z); b0.w = fmaf(w0, p10.w, b0.w);
    }
    a0.x += a1.x; a0.y += a1.y; a0.z += a1.z; a0.w += a1.w;
    b0.x += b1.x; b0.y += b1.y; b0.z += b1.z; b0.w += b1.w;
    size_t obase = (size_t)(row + row_off) * D;
    ((float4*)(o0 + obase))[lane] = a0;
    ((float4*)(o1 + obase))[lane] = b0;
}

__global__ void spmm1_kernel(const int* __restrict__ rowptr,
                             const int* __restrict__ cols,
                             const float* __restrict__ vals,
                             const float* __restrict__ x,
                             float* __restrict__ o,
                             float* __restrict__ cge,
                             int mode, int n_rows) {
    spmm1_device(rowptr, cols, vals, x, o, cge, mode, n_rows, 0, blockIdx.x);
}

// ---------------- conflict-free FFMA2 GEMM ------------------
#define GM_BM 64
#define GM_BN 64
#define GM_BK 16
#define MBLK  469   // ceil(30000 / 64)

struct GemmJob {
    const float* A; const float* A2; const float* B;
    const float* bias; const float* F;
    float* out; int M; int K; int mode; int splits;
};

__device__ void gemm_device(const GemmJob j, int local) {
    __shared__ float As[GM_BK][GM_BM];     // 4KB, transposed A
    __shared__ float Bs[GM_BK * GM_BN];    // 4KB, linear [k*64 + n]

    int split = local / MBLK;
    int mblk  = local % MBLK;
    int Kc    = j.K / j.splits;
    int kbeg  = split * Kc;
    int kend  = kbeg + Kc;

    int tid = threadIdx.x;
    int tx = tid & 15;
    int ty = tid >> 4;
    int m0 = mblk * GM_BM;

    int a_row = tid >> 1;
    int a_koff = (tid & 1) * 8;
    int a_gr = m0 + a_row;
    int b_half = tid >> 6;
    int b_c = tid & 63;

    unsigned long long acc[4][4];
    #pragma unroll
    for (int r = 0; r < 4; r++)
        #pragma unroll
        for (int c = 0; c < 4; c++) acc[r][c] = 0ull;

    for (int k0 = kbeg; k0 < kend; k0 += GM_BK) {
        {
            const float* arow  = j.A + (size_t)a_gr * j.K + k0 + a_koff;
            float4 av0 = make_float4(0.f,0.f,0.f,0.f);
            float4 av1 = make_float4(0.f,0.f,0.f,0.f);
            if (a_gr < j.M) {
                av0 = *(const float4*)(arow);
                av1 = *(const float4*)(arow + 4);
                if (j.A2) {
                    const float* arow2 = j.A2 + (size_t)a_gr * j.K + k0 + a_koff;
                    float4 b0 = *(const float4*)(arow2);
                    float4 b1 = *(const float4*)(arow2 + 4);
                    av0.x -= b0.x; av0.y -= b0.y; av0.z -= b0.z; av0.w -= b0.w;
                    av1.x -= b1.x; av1.y -= b1.y; av1.z -= b1.z; av1.w -= b1.w;
                }
            }
            As[a_koff + 0][a_row] = av0.x;
            As[a_koff + 1][a_row] = av0.y;
            As[a_koff + 2][a_row] = av0.z;
            As[a_koff + 3][a_row] = av0.w;
            As[a_koff + 4][a_row] = av1.x;
            As[a_koff + 5][a_row] = av1.y;
            As[a_koff + 6][a_row] = av1.z;
            As[a_koff + 7][a_row] = av1.w;
        }
        {
            #pragma unroll
            for (int i = 0; i < 8; i++) {
                int kr = 2 * i + b_half;
                Bs[i * 128 + tid] = __ldg(j.B + (size_t)(k0 + kr) * GM_BN + b_c);
            }
        }
        __syncthreads();

        #pragma unroll
        for (int kk = 0; kk < GM_BK; kk++) {
            ulonglong2 a01 = *(const ulonglong2*)&As[kk][ty * 8 + 0];
            ulonglong2 a23 = *(const ulonglong2*)&As[kk][ty * 8 + 4];
            float bs0 = Bs[kk * 64 + tx];
            float bs1 = Bs[kk * 64 + tx + 16];
            float bs2 = Bs[kk * 64 + tx + 32];
            float bs3 = Bs[kk * 64 + tx + 48];
            unsigned long long ar[4] = {a01.x, a01.y, a23.x, a23.y};
            unsigned long long bc[4] = {pack2_(bs0, bs0), pack2_(bs1, bs1),
                                        pack2_(bs2, bs2), pack2_(bs3, bs3)};
            #pragma unroll
            for (int r = 0; r < 4; r++)
                #pragma unroll
                for (int c = 0; c < 4; c++)
                    acc[r][c] = fma2_(ar[r], bc[c], acc[r][c]);
        }
        __syncthreads();
    }

    #pragma unroll
    for (int rp = 0; rp < 4; rp++) {
        int gm0 = m0 + ty * 8 + rp * 2;
        bool ok0 = gm0 < j.M, ok1 = gm0 + 1 < j.M;
        #pragma unroll
        for (int c = 0; c < 4; c++) {
            float2 p = unpack2_(acc[rp][c]);
            int gn = tx + 16 * c;
            float v0 = p.x, v1 = p.y;
            if (j.mode == 1) {
                float bs = __ldg(j.bias + gn);
                if (ok0) v0 = sigmoidf_(v0 + bs) * __ldg(j.F + (size_t)gm0 * 64 + gn);
                if (ok1) v1 = sigmoidf_(v1 + bs) * __ldg(j.F + (size_t)(gm0 + 1) * 64 + gn);
            }
            if (j.mode == 2) {
                if (ok0) red_add_f(j.out + (size_t)gm0 * 64 + gn, v0);
                if (ok1) red_add_f(j.out + (size_t)(gm0 + 1) * 64 + gn, v1);
            } else {
                if (ok0) j.out[(size_t)gm0 * 64 + gn] = v0;
                if (ok1) j.out[(size_t)(gm0 + 1) * 64 + gn] = v1;
            }
        }
    }
}

__global__ void __launch_bounds__(128) gemm1_kernel(GemmJob j) {
    gemm_device(j, blockIdx.x);
}

// ---------------- adjacency 4-channel SpMM ----------------
__global__ void spmm4_kernel(const int* __restrict__ rowptr,
                             const int* __restrict__ cols,
                             const float* __restrict__ vals,
                             const float* __restrict__ x0, const float* __restrict__ x1,
                             const float* __restrict__ x2, const float* __restrict__ x3,
                             float* __restrict__ o0, float* __restrict__ o1,
                             float* __restrict__ o2, float* __restrict__ o3,
                             int n_rows) {
    int t = blockIdx.x * blockDim.x + threadIdx.x;
    int row = t >> 4, lane = t & 15;
    if (row >= n_rows) return;
    int start = __ldg(rowptr + row), end = __ldg(rowptr + row + 1);
    float4 a0 = make_float4(0.f,0.f,0.f,0.f);
    float4 a1 = make_float4(0.f,0.f,0.f,0.f);
    float4 a2 = make_float4(0.f,0.f,0.f,0.f);
    float4 a3 = make_float4(0.f,0.f,0.f,0.f);
    for (int k = start; k < end; k++) {
        int   c = __ldg(cols + k);
        float w = __ldg(vals + k);
        size_t off = (size_t)c * D;
        float4 p0 = __ldg((const float4*)(x0 + off) + lane);
        float4 p1 = __ldg((const float4*)(x1 + off) + lane);
        float4 p2 = __ldg((const float4*)(x2 + off) + lane);
        float4 p3 = __ldg((const float4*)(x3 + off) + lane);
        a0.x = fmaf(w, p0.x, a0.x); a0.y = fmaf(w, p0.y, a0.y);
        a0.z = fmaf(w, p0.z, a0.z); a0.w = fmaf(w, p0.w, a0.w);
        a1.x = fmaf(w, p1.x, a1.x); a1.y = fmaf(w, p1.y, a1.y);
        a1.z = fmaf(w, p1.z, a1.z); a1.w = fmaf(w, p1.w, a1.w);
        a2.x = fmaf(w, p2.x, a2.x); a2.y = fmaf(w, p2.y, a2.y);
        a2.z = fmaf(w, p2.z, a2.z); a2.w = fmaf(w, p2.w, a2.w);
        a3.x = fmaf(w, p3.x, a3.x); a3.y = fmaf(w, p3.y, a3.y);
        a3.z = fmaf(w, p3.z, a3.z); a3.w = fmaf(w, p3.w, a3.w);
    }
    size_t obase = (size_t)row * D;
    ((float4*)(o0 + obase))[lane] = a0;
    ((float4*)(o1 + obase))[lane] = a1;
    ((float4*)(o2 + obase))[lane] = a2;
    ((float4*)(o3 + obase))[lane] = a3;
}

// ---------------- modal halves: ii jobs (3) and uu jobs (3) -------------------
#define JOB_BLOCKS 1875
__global__ void modal_ii_kernel(const int* __restrict__ rowptr,
                                const int* __restrict__ colss,
                                const float* __restrict__ valss,
                                const float* __restrict__ persv, const float* __restrict__ perst,
                                const float* __restrict__ comv, const float* __restrict__ comt,
                                float* __restrict__ pev, float* __restrict__ pet,
                                float* __restrict__ cev, float* __restrict__ cet) {
    int b = blockIdx.x;
    int job = b / JOB_BLOCKS;
    int lb = b % JOB_BLOCKS;
    switch (job) {
    case 0: spmm1_device(rowptr + RPO_IMG_II, colss + SEG_IMG_II, valss + SEG_IMG_II,
                         persv, pev, nullptr, 0, N_ITEMS, N_USERS, lb); break;
    case 1: spmm1_device(rowptr + RPO_TXT_II, colss + SEG_TXT_II, valss + SEG_TXT_II,
                         perst, pet, nullptr, 0, N_ITEMS, N_USERS, lb); break;
    default: spmm2_device(rowptr + RPO_CII, colss + SEG_CII, valss + SEG_CII,
                         comv, comt, cev, cet, N_ITEMS, N_USERS, lb); break;
    }
}

__global__ void modal_uu_kernel(const int* __restrict__ rowptr,
                                const int* __restrict__ colss,
                                const float* __restrict__ valss,
                                const float* __restrict__ upv, const float* __restrict__ upt,
                                const float* __restrict__ ucv, const float* __restrict__ uct,
                                float* __restrict__ pev, float* __restrict__ pet,
                                float* __restrict__ cev, float* __restrict__ cet) {
    int b = blockIdx.x;
    int job = b / JOB_BLOCKS;
    int lb = b % JOB_BLOCKS;
    switch (job) {
    case 0: spmm1_device(rowptr + RPO_IMG_UU, colss + SEG_IMG_UU, valss + SEG_IMG_UU,
                         upv, pev, nullptr, 0, N_USERS, 0, lb); break;
    case 1: spmm1_device(rowptr + RPO_TXT_UU, colss + SEG_TXT_UU, valss + SEG_TXT_UU,
                         upt, pet, nullptr, 0, N_USERS, 0, lb); break;
    default: spmm2_device(rowptr + RPO_CUU, colss + SEG_CUU, valss + SEG_CUU,
                         ucv, uct, cev, cet, N_USERS, 0, lb); break;
    }
}

// ---------------- final ----------------
__global__ void final_kernel(const float* __restrict__ cge,
                             const float* __restrict__ pev,
                             const float* __restrict__ pet,
                             const float* __restrict__ cev,
                             const float* __restrict__ cet,
                             const float* __restrict__ att,
                             float* __restrict__ out) {
    int warp = (blockIdx.x * blockDim.x + threadIdx.x) >> 5;
    int lane = threadIdx.x & 31;
    if (warp >= N_NODES) return;
    float a0 = __ldg(att + 0), a1 = __ldg(att + 1);
    float mx = fmaxf(a0, a1);
    float e0 = __expf(a0 - mx), e1 = __expf(a1 - mx);
    float inv = 1.0f / (e0 + e1);
    float w0 = e0 * inv, w1 = e1 * inv;

    size_t base = (size_t)warp * D;
    float p0 = w0 * pev[base + lane]      + w1 * pet[base + lane];
    float p1 = w0 * pev[base + 32 + lane] + w1 * pet[base + 32 + lane];
    float c0 = w0 * cev[base + lane]      + w1 * cet[base + lane];
    float c1 = w0 * cev[base + 32 + lane] + w1 * cet[base + 32 + lane];

    float sp = p0 * p0 + p1 * p1;
    float sc = c0 * c0 + c1 * c1;
    #pragma unroll
    for (int o = 16; o; o >>= 1) {
        sp += __shfl_xor_sync(0xffffffffu, sp, o);
        sc += __shfl_xor_sync(0xffffffffu, sc, o);
    }
    float ip = 1.0f / (sqrtf(sp) + 1e-12f);
    float ic = 1.0f / (sqrtf(sc) + 1e-12f);
    const float third = 1.0f / 3.0f;
    out[base + lane]      = cge[base + lane] * third      + 0.3f * p0 * ip + 0.8f * c0 * ic;
    out[base + 32 + lane] = cge[base + 32 + lane] * third + 0.3f * p1 * ip + 0.8f * c1 * ic;
}

// ---------------- host ----------------
static inline unsigned gdiv(long long t, int b) { return (unsigned)((t + b - 1) / b); }

extern "C" void kernel_launch(void* const* d_in, const int* in_sizes, int n_in,
                              void* d_out, int out_size) {
    const float* user_emb    = (const float*)d_in[0];
    const float* item_emb    = (const float*)d_in[1];
    const float* image_feats = (const float*)d_in[2];
    const float* text_feats  = (const float*)d_in[3];
    const float* trs_v       = (const float*)d_in[4];
    const float* trs_t       = (const float*)d_in[5];
    const float* gate_v      = (const float*)d_in[6];
    const float* gate1_v     = (const float*)d_in[7];
    const float* gate_t      = (const float*)d_in[8];
    const float* gate1_t     = (const float*)d_in[9];
    const float* bias_v      = (const float*)d_in[10];
    const float* bias1_v     = (const float*)d_in[11];
    const float* bias_t      = (const float*)d_in[12];
    const float* bias1_t     = (const float*)d_in[13];
    const float* att         = (const float*)d_in[14];
    const float* num_inters  = (const float*)d_in[15];
    const float* vals_norm   = (const float*)d_in[16];
    const float* vals_adj    = (const float*)d_in[17];
    const float* vals_img_ii = (const float*)d_in[18];
    const float* vals_txt_ii = (const float*)d_in[19];
    const float* vals_img_uu = (const float*)d_in[20];
    const float* vals_txt_uu = (const float*)d_in[21];
    const float* vals_cii    = (const float*)d_in[22];
    const float* vals_cuu    = (const float*)d_in[23];
    const int* idx_norm      = (const int*)d_in[24];
    const int* idx_adj       = (const int*)d_in[25];
    const int* idx_img_ii    = (const int*)d_in[26];
    const int* idx_txt_ii    = (const int*)d_in[27];
    const int* idx_img_uu    = (const int*)d_in[28];
    const int* idx_txt_uu    = (const int*)d_in[29];
    const int* idx_cii       = (const int*)d_in[30];
    const int* idx_cuu       = (const int*)d_in[31];
    float* out = (float*)d_out;

    float *egoA, *egoB, *cge, *fv, *comv, *persv, *ft, *comt, *perst;
    float *upv, *ucv, *upt, *uct, *pev, *cev, *pet, *cet;
    int *counts, *rowptr, *cursor, *colss; float* valss;
    cudaGetSymbolAddress((void**)&egoA,  g_egoA);
    cudaGetSymbolAddress((void**)&egoB,  g_egoB);
    cudaGetSymbolAddress((void**)&cge,   g_cge);
    cudaGetSymbolAddress((void**)&fv,    g_fv);
    cudaGetSymbolAddress((void**)&comv,  g_comv);
    cudaGetSymbolAddress((void**)&persv, g_persv);
    cudaGetSymbolAddress((void**)&ft,    g_ft);
    cudaGetSymbolAddress((void**)&comt,  g_comt);
    cudaGetSymbolAddress((void**)&perst, g_perst);
    cudaGetSymbolAddress((void**)&upv,   g_upv);
    cudaGetSymbolAddress((void**)&ucv,   g_ucv);
    cudaGetSymbolAddress((void**)&upt,   g_upt);
    cudaGetSymbolAddress((void**)&uct,   g_uct);
    cudaGetSymbolAddress((void**)&pev,   g_pev);
    cudaGetSymbolAddress((void**)&cev,   g_cev);
    cudaGetSymbolAddress((void**)&pet,   g_pet);
    cudaGetSymbolAddress((void**)&cet,   g_cet);
    cudaGetSymbolAddress((void**)&counts, g_counts);
    cudaGetSymbolAddress((void**)&rowptr, g_rowptr);
    cudaGetSymbolAddress((void**)&cursor, g_cursor);
    cudaGetSymbolAddress((void**)&colss,  g_colss);
    cudaGetSymbolAddress((void**)&valss,  g_valss);

    // streams + events (handles only; created once)
    static cudaStream_t s2 = nullptr, s3 = nullptr;
    static cudaEvent_t evFork = nullptr, evCur = nullptr, evScR = nullptr;
    static cudaEvent_t evG1v = nullptr, evG1t = nullptr, evSp4 = nullptr;
    if (!s2) {
        cudaStreamCreateWithFlags(&s2, cudaStreamNonBlocking);
        cudaStreamCreateWithFlags(&s3, cudaStreamNonBlocking);
        cudaEventCreateWithFlags(&evFork, cudaEventDisableTiming);
        cudaEventCreateWithFlags(&evCur,  cudaEventDisableTiming);
        cudaEventCreateWithFlags(&evScR,  cudaEventDisableTiming);
        cudaEventCreateWithFlags(&evG1v,  cudaEventDisableTiming);
        cudaEventCreateWithFlags(&evG1t,  cudaEventDisableTiming);
        cudaEventCreateWithFlags(&evSp4,  cudaEventDisableTiming);
    }

    // ---- stream 0: shared memsets, then fork ----
    cudaMemsetAsync(counts, 0, RP_TOTAL * sizeof(int), 0);
    const size_t FB = (size_t)N_ITEMS * D * sizeof(float);
    cudaMemsetAsync(fv, 0, FB, 0);
    cudaMemsetAsync(ft, 0, FB, 0);
    cudaEventRecord(evFork, 0);

    // ---- chain B-img (s2): img GEMM -> gate_v -> gate1_v ----
    cudaStreamWaitEvent(s2, evFork, 0);
    GemmJob jImg  = { image_feats, nullptr, trs_v,   nullptr,  nullptr, fv,    N_ITEMS, IMG_DIM, 2, 4 };
    GemmJob jGv   = { fv,          nullptr, gate_v,  bias_v,   fv,      comv,  N_ITEMS, 64,      1, 1 };
    GemmJob jG1v  = { fv,          comv,    gate1_v, bias1_v,  fv,      persv, N_ITEMS, 64,      1, 1 };
    gemm1_kernel<<<MBLK * 4, 128, 0, s2>>>(jImg);
    gemm1_kernel<<<MBLK, 128, 0, s2>>>(jGv);
    gemm1_kernel<<<MBLK, 128, 0, s2>>>(jG1v);
    cudaEventRecord(evG1v, s2);

    // ---- chain B-txt (s3): txt GEMM -> gate_t -> gate1_t ----
    cudaStreamWaitEvent(s3, evFork, 0);
    GemmJob jTxt  = { text_feats,  nullptr, trs_t,   nullptr,  nullptr, ft,    N_ITEMS, TXT_DIM, 2, 2 };
    GemmJob jGt   = { ft,          nullptr, gate_t,  bias_t,   ft,      comt,  N_ITEMS, 64,      1, 1 };
    GemmJob jG1t  = { ft,          comt,    gate1_t, bias1_t,  ft,      perst, N_ITEMS, 64,      1, 1 };
    gemm1_kernel<<<MBLK * 2, 128, 0, s3>>>(jTxt);
    gemm1_kernel<<<MBLK, 128, 0, s3>>>(jGt);
    gemm1_kernel<<<MBLK, 128, 0, s3>>>(jG1t);
    cudaEventRecord(evG1t, s3);

    // ---- chain A (stream 0): CSR build + norm-segment scatter + norms ----
    build1_kernel<<<HIST_BLOCKS + CAT_BLOCKS, 256>>>(
        idx_norm, idx_adj, idx_img_ii, idx_txt_ii, idx_img_uu, idx_txt_uu, idx_cii, idx_cuu,
        counts, user_emb, item_emb, egoA);
    scan_kernel<<<8, 1024>>>(counts, rowptr);
    cudaMemcpyAsync(cursor, rowptr, RP_TOTAL * sizeof(int), cudaMemcpyDeviceToDevice, 0);
    cudaEventRecord(evCur, 0);

    // norm-segment scatter on stream 0 (critical path for norm layers)
    scatter_kernel<<<gdiv(NNZ_NORM, 256), 256>>>(
        idx_norm, idx_adj, idx_img_ii, idx_txt_ii, idx_img_uu, idx_txt_uu, idx_cii, idx_cuu,
        vals_norm, vals_adj, vals_img_ii, vals_txt_ii,
        vals_img_uu, vals_txt_uu, vals_cii, vals_cuu,
        num_inters, cursor, colss, valss, 0, NNZ_NORM);

    // rest-segment scatter on s3 (after txt chain; needs cursor ready)
    cudaStreamWaitEvent(s3, evCur, 0);
    scatter_kernel<<<gdiv(NNZ_TOT - NNZ_NORM, 256), 256, 0, s3>>>(
        idx_norm, idx_adj, idx_img_ii, idx_txt_ii, idx_img_uu, idx_txt_uu, idx_cii, idx_cuu,
        vals_norm, vals_adj, vals_img_ii, vals_txt_ii,
        vals_img_uu, vals_txt_uu, vals_cii, vals_cuu,
        num_inters, cursor, colss, valss, NNZ_NORM, NNZ_TOT - NNZ_NORM);
    cudaEventRecord(evScR, s3);

    // spmm4 on s2: needs gates1 of both modalities + rest scatter
    cudaStreamWaitEvent(s2, evScR, 0);
    cudaStreamWaitEvent(s2, evG1t, 0);
    unsigned gusers = gdiv((long long)N_USERS * 16, 256);
    spmm4_kernel<<<gusers, 256, 0, s2>>>(rowptr + RPO_ADJ, colss + SEG_ADJ, valss + SEG_ADJ,
                                         persv, comv, perst, comt,
                                         upv, ucv, upt, uct, N_USERS);
    cudaEventRecord(evSp4, s2);

    // ---- chain A continues: norm layers ----
    const int* rpN = rowptr + RPO_NORM;
    const int* clN = colss + SEG_NORM;
    const float* vlN = valss + SEG_NORM;
    unsigned gnodes = gdiv((long long)N_NODES * 16, 256);
    spmm1_kernel<<<gnodes, 256>>>(rpN, clN, vlN, egoA, egoB, cge, 1, N_NODES);
    spmm1_kernel<<<gnodes, 256>>>(rpN, clN, vlN, egoB, egoA, cge, 2, N_NODES);
    spmm1_kernel<<<gnodes, 256>>>(rpN, clN, vlN, egoA, egoB, cge, 2, N_NODES);

    // ---- modal-ii on stream 0 (needs gates1 of both + rest scatter) ----
    cudaStreamWaitEvent(0, evG1v, 0);
    cudaStreamWaitEvent(0, evG1t, 0);
    cudaStreamWaitEvent(0, evScR, 0);
    modal_ii_kernel<<<3 * JOB_BLOCKS, 256>>>(rowptr, colss, valss,
                                             persv, perst, comv, comt,
                                             pev, pet, cev, cet);

    // ---- modal-uu (needs spmm4) then final ----
    cudaStreamWaitEvent(0, evSp4, 0);
    modal_uu_kernel<<<3 * JOB_BLOCKS, 256>>>(rowptr, colss, valss,
                                             upv, upt, ucv, uct,
                                             pev, pet, cev, cet);

    final_kernel<<<gdiv((long long)N_NODES * 32, 256), 256>>>(cge, pev, pet, cev, cet, att, out);
}

// round 16
// speedup vs baseline: 1.0343x; 1.0343x over previous
#include <cuda_runtime.h>
#include <cuda_bf16.h>
#include <cstdint>

#define N_USERS 30000
#define N_ITEMS 30000
#define N_NODES 60000
#define D 64
#define IMG_DIM 2048
#define TXT_DIM 384
#define NNZ_NORM 2000000
#define NNZ_ADJ  1000000
#define NNZ_G    150000
#define NNZ_TOT  3900000

#define SEG_NORM   0
#define SEG_ADJ    2000000
#define SEG_IMG_II 3000000
#define SEG_TXT_II 3150000
#define SEG_IMG_UU 3300000
#define SEG_TXT_UU 3450000
#define SEG_CII    3600000
#define SEG_CUU    3750000

#define RPO_NORM   0
#define RPO_ADJ    60001
#define RPO_IMG_II 90002
#define RPO_TXT_II 120003
#define RPO_IMG_UU 150004
#define RPO_TXT_UU 180005
#define RPO_CII    210006
#define RPO_CUU    240007
#define RP_TOTAL   270008

// ---------------- scratch ----------------
__device__ float g_egoA[N_NODES * D];
__device__ float g_egoB[N_NODES * D];
__device__ float g_cge [N_NODES * D];

__device__ float g_fv   [N_ITEMS * D];
__device__ float g_comv [N_ITEMS * D];
__device__ float g_persv[N_ITEMS * D];
__device__ float g_ft   [N_ITEMS * D];
__device__ float g_comt [N_ITEMS * D];
__device__ float g_perst[N_ITEMS * D];

__device__ float g_upv[N_USERS * D];
__device__ float g_ucv[N_USERS * D];
__device__ float g_upt[N_USERS * D];
__device__ float g_uct[N_USERS * D];

__device__ float g_pev[N_NODES * D];
__device__ float g_cev[N_NODES * D];
__device__ float g_pet[N_NODES * D];
__device__ float g_cet[N_NODES * D];

__device__ int   g_counts[RP_TOTAL];
__device__ int   g_rowptr[RP_TOTAL];
__device__ int   g_cursor[RP_TOTAL];
__device__ int   g_colss [NNZ_TOT];
__device__ float g_valss [NNZ_TOT];

__constant__ int c_nrows[8] = {60000,30000,30000,30000,30000,30000,30000,30000};
__constant__ int c_rpoff[8] = {RPO_NORM,RPO_ADJ,RPO_IMG_II,RPO_TXT_II,RPO_IMG_UU,RPO_TXT_UU,RPO_CII,RPO_CUU};

// ---------------- helpers ----------------
__device__ __forceinline__ float sigmoidf_(float x) {
    return 1.0f / (1.0f + __expf(-x));
}
__device__ __forceinline__ unsigned long long fma2_(unsigned long long a, unsigned long long b,
                                                    unsigned long long c) {
    unsigned long long d;
    asm("fma.rn.f32x2 %0, %1, %2, %3;" : "=l"(d) : "l"(a), "l"(b), "l"(c));
    return d;
}
__device__ __forceinline__ unsigned long long pack2_(float lo, float hi) {
    unsigned long long d;
    asm("mov.b64 %0, {%1, %2};" : "=l"(d) : "f"(lo), "f"(hi));
    return d;
}
__device__ __forceinline__ float2 unpack2_(unsigned long long v) {
    float2 r;
    asm("mov.b64 {%0, %1}, %2;" : "=f"(r.x), "=f"(r.y) : "l"(v));
    return r;
}
__device__ __forceinline__ void red_add_f(float* addr, float v) {
    asm volatile("red.global.add.f32 [%0], %1;" :: "l"(addr), "f"(v) : "memory");
}

// ---------------- CSR build ----------------
#define HIST_BLOCKS 15235   // ceil(NNZ_TOT/256)
#define CAT_BLOCKS  3750    // N_NODES*D/4/256

__global__ void build1_kernel(const int* __restrict__ i0, const int* __restrict__ i1,
                              const int* __restrict__ i2, const int* __restrict__ i3,
                              const int* __restrict__ i4, const int* __restrict__ i5,
                              const int* __restrict__ i6, const int* __restrict__ i7,
                              int* __restrict__ counts,
                              const float* __restrict__ u, const float* __restrict__ it,
                              float* __restrict__ ego) {
    if (blockIdx.x < HIST_BLOCKS) {
        int gid = blockIdx.x * 256 + threadIdx.x;
        if (gid >= NNZ_TOT) return;
        const int* rows; int i, rpo;
        if      (gid < SEG_ADJ)    { rows = i0; i = gid - SEG_NORM;   rpo = RPO_NORM;   }
        else if (gid < SEG_IMG_II) { rows = i1; i = gid - SEG_ADJ;    rpo = RPO_ADJ;    }
        else if (gid < SEG_TXT_II) { rows = i2; i = gid - SEG_IMG_II; rpo = RPO_IMG_II; }
        else if (gid < SEG_IMG_UU) { rows = i3; i = gid - SEG_TXT_II; rpo = RPO_TXT_II; }
        else if (gid < SEG_TXT_UU) { rows = i4; i = gid - SEG_IMG_UU; rpo = RPO_IMG_UU; }
        else if (gid < SEG_CII)    { rows = i5; i = gid - SEG_TXT_UU; rpo = RPO_TXT_UU; }
        else if (gid < SEG_CUU)    { rows = i6; i = gid - SEG_CII;    rpo = RPO_CII;    }
        else                       { rows = i7; i = gid - SEG_CUU;    rpo = RPO_CUU;    }
        atomicAdd(&counts[rpo + __ldg(rows + i)], 1);
    } else {
        int i = (blockIdx.x - HIST_BLOCKS) * 256 + threadIdx.x;
        int n_half4 = (N_USERS * D) / 4;
        int n_tot4  = (N_NODES * D) / 4;
        if (i >= n_tot4) return;
        const float4* src = (i < n_half4) ? (const float4*)u : (const float4*)it;
        int j = (i < n_half4) ? i : (i - n_half4);
        ((float4*)ego)[i] = src[j];
    }
}

__global__ void scan_kernel(const int* __restrict__ counts, int* __restrict__ rowptr) {
    int m = blockIdx.x;
    int n = c_nrows[m];
    const int* cnt = counts + c_rpoff[m];
    int* rp = rowptr + c_rpoff[m];
    __shared__ int part[1024];
    int tid = threadIdx.x;
    int chunk = (n + 1023) >> 10;
    int lo = tid * chunk;
    int hi = lo + chunk; if (hi > n) hi = n;
    int s = 0;
    for (int i = lo; i < hi; i++) s += cnt[i];
    part[tid] = s;
    __syncthreads();
    for (int off = 1; off < 1024; off <<= 1) {
        int v = (tid >= off) ? part[tid - off] : 0;
        __syncthreads();
        part[tid] += v;
        __syncthreads();
    }
    int base = (tid == 0) ? 0 : part[tid - 1];
    for (int i = lo; i < hi; i++) { rp[i] = base; base += cnt[i]; }
    if (lo < n && hi == n) rp[n] = base;
}

__global__ void scatter_kernel(const int* __restrict__ i0, const int* __restrict__ i1,
                               const int* __restrict__ i2, const int* __restrict__ i3,
                               const int* __restrict__ i4, const int* __restrict__ i5,
                               const int* __restrict__ i6, const int* __restrict__ i7,
                               const float* __restrict__ v0, const float* __restrict__ v1,
                               const float* __restrict__ v2, const float* __restrict__ v3,
                               const float* __restrict__ v4, const float* __restrict__ v5,
                               const float* __restrict__ v6, const float* __restrict__ v7,
                               const float* __restrict__ num_inters,
                               int* __restrict__ cursor,
                               int* __restrict__ cols_s, float* __restrict__ vals_s) {
    int gid = blockIdx.x * blockDim.x + threadIdx.x;
    if (gid >= NNZ_TOT) return;
    const int* idx; const float* vls; int i, rpo, seg, nz; bool sc;
    if      (gid < SEG_ADJ)    { idx=i0; vls=v0; i=gid-SEG_NORM;   rpo=RPO_NORM;   seg=SEG_NORM;   nz=NNZ_NORM; sc=false; }
    else if (gid < SEG_IMG_II) { idx=i1; vls=v1; i=gid-SEG_ADJ;    rpo=RPO_ADJ;    seg=SEG_ADJ;    nz=NNZ_ADJ;  sc=false; }
    else if (gid < SEG_TXT_II) { idx=i2; vls=v2; i=gid-SEG_IMG_II; rpo=RPO_IMG_II; seg=SEG_IMG_II; nz=NNZ_G;    sc=false; }
    else if (gid < SEG_IMG_UU) { idx=i3; vls=v3; i=gid-SEG_TXT_II; rpo=RPO_TXT_II; seg=SEG_TXT_II; nz=NNZ_G;    sc=false; }
    else if (gid < SEG_TXT_UU) { idx=i4; vls=v4; i=gid-SEG_IMG_UU; rpo=RPO_IMG_UU; seg=SEG_IMG_UU; nz=NNZ_G;    sc=true;  }
    else if (gid < SEG_CII)    { idx=i5; vls=v5; i=gid-SEG_TXT_UU; rpo=RPO_TXT_UU; seg=SEG_TXT_UU; nz=NNZ_G;    sc=true;  }
    else if (gid < SEG_CUU)    { idx=i6; vls=v6; i=gid-SEG_CII;    rpo=RPO_CII;    seg=SEG_CII;    nz=NNZ_G;    sc=false; }
    else                       { idx=i7; vls=v7; i=gid-SEG_CUU;    rpo=RPO_CUU;    seg=SEG_CUU;    nz=NNZ_G;    sc=true;  }
    int r = __ldg(idx + i);
    int c = __ldg(idx + nz + i);
    float v = __ldg(vls + i);
    if (sc) v *= __ldg(num_inters + c);
    int pos = atomicAdd(&cursor[rpo + r], 1);
    cols_s[seg + pos] = c;
    vals_s[seg + pos] = v;
}

// ---------------- SpMM device building blocks ----------------

__device__ __forceinline__ void spmm1_device(const int* __restrict__ rowptr,
                                             const int* __restrict__ cols,
                                             const float* __restrict__ vals,
                                             const float* __restrict__ x,
                                             float* __restrict__ o,
                                             float* __restrict__ cge,
                                             int mode, int n_rows, int row_off, int blk) {
    int t = blk * 256 + threadIdx.x;
    int row = t >> 4, lane = t & 15;
    if (row >= n_rows) return;
    int start = __ldg(rowptr + row), end = __ldg(rowptr + row + 1);
    float4 a0 = make_float4(0.f,0.f,0.f,0.f);
    float4 a1 = make_float4(0.f,0.f,0.f,0.f);
    float4 a2 = make_float4(0.f,0.f,0.f,0.f);
    float4 a3 = make_float4(0.f,0.f,0.f,0.f);
    int k = start;
    for (; k + 4 <= end; k += 4) {
        int   c0 = __ldg(cols + k), c1 = __ldg(cols + k + 1);
        int   c2 = __ldg(cols + k + 2), c3 = __ldg(cols + k + 3);
        float w0 = __ldg(vals + k), w1 = __ldg(vals + k + 1);
        float w2 = __ldg(vals + k + 2), w3 = __ldg(vals + k + 3);
        float4 p0 = __ldg((const float4*)(x + (size_t)c0 * D) + lane);
        float4 p1 = __ldg((const float4*)(x + (size_t)c1 * D) + lane);
        float4 p2 = __ldg((const float4*)(x + (size_t)c2 * D) + lane);
        float4 p3 = __ldg((const float4*)(x + (size_t)c3 * D) + lane);
        a0.x = fmaf(w0, p0.x, a0.x); a0.y = fmaf(w0, p0.y, a0.y);
        a0.z = fmaf(w0, p0.z, a0.z); a0.w = fmaf(w0, p0.w, a0.w);
        a1.x = fmaf(w1, p1.x, a1.x); a1.y = fmaf(w1, p1.y, a1.y);
        a1.z = fmaf(w1, p1.z, a1.z); a1.w = fmaf(w1, p1.w, a1.w);
        a2.x = fmaf(w2, p2.x, a2.x); a2.y = fmaf(w2, p2.y, a2.y);
        a2.z = fmaf(w2, p2.z, a2.z); a2.w = fmaf(w2, p2.w, a2.w);
        a3.x = fmaf(w3, p3.x, a3.x); a3.y = fmaf(w3, p3.y, a3.y);
        a3.z = fmaf(w3, p3.z, a3.z); a3.w = fmaf(w3, p3.w, a3.w);
    }
    for (; k < end; k++) {
        int   c0 = __ldg(cols + k);
        float w0 = __ldg(vals + k);
        float4 p0 = __ldg((const float4*)(x + (size_t)c0 * D) + lane);
        a0.x = fmaf(w0, p0.x, a0.x); a0.y = fmaf(w0, p0.y, a0.y);
        a0.z = fmaf(w0, p0.z, a0.z); a0.w = fmaf(w0, p0.w, a0.w);
    }
    a0.x += a1.x + a2.x + a3.x;
    a0.y += a1.y + a2.y + a3.y;
    a0.z += a1.z + a2.z + a3.z;
    a0.w += a1.w + a2.w + a3.w;
    size_t obase = (size_t)(row + row_off) * D;
    ((float4*)(o + obase))[lane] = a0;
    if (mode == 1) {
        ((float4*)(cge + obase))[lane] = a0;
    } else if (mode == 2) {
        float4 t4 = ((float4*)(cge + obase))[lane];
        t4.x += a0.x; t4.y += a0.y; t4.z += a0.z; t4.w += a0.w;
        ((float4*)(cge + obase))[lane] = t4;
    }
}

__device__ __forceinline__ void spmm2_device(const int* __restrict__ rowptr,
                                             const int* __restrict__ cols,
                                             const float* __restrict__ vals,
                                             const float* __restrict__ x0, const float* __restrict__ x1,
                                             float* __restrict__ o0, float* __restrict__ o1,
                                             int n_rows, int row_off, int blk) {
    int t = blk * 256 + threadIdx.x;
    int row = t >> 4, lane = t & 15;
    if (row >= n_rows) return;
    int start = __ldg(rowptr + row), end = __ldg(rowptr + row + 1);
    float4 a0 = make_float4(0.f,0.f,0.f,0.f);
    float4 a1 = make_float4(0.f,0.f,0.f,0.f);
    float4 b0 = make_float4(0.f,0.f,0.f,0.f);
    float4 b1 = make_float4(0.f,0.f,0.f,0.f);
    int k = start;
    for (; k + 2 <= end; k += 2) {
        int   c0 = __ldg(cols + k), c1 = __ldg(cols + k + 1);
        float w0 = __ldg(vals + k), w1 = __ldg(vals + k + 1);
        size_t f0 = (size_t)c0 * D, f1 = (size_t)c1 * D;
        float4 p00 = __ldg((const float4*)(x0 + f0) + lane);
        float4 p10 = __ldg((const float4*)(x1 + f0) + lane);
        float4 p01 = __ldg((const float4*)(x0 + f1) + lane);
        float4 p11 = __ldg((const float4*)(x1 + f1) + lane);
        a0.x = fmaf(w0, p00.x, a0.x); a0.y = fmaf(w0, p00.y, a0.y);
        a0.z = fmaf(w0, p00.z, a0.z); a0.w = fmaf(w0, p00.w, a0.w);
        b0.x = fmaf(w0, p10.x, b0.x); b0.y = fmaf(w0, p10.y, b0.y);
        b0.z = fmaf(w0, p10.z, b0.z); b0.w = fmaf(w0, p10.w, b0.w);
        a1.x = fmaf(w1, p01.x, a1.x); a1.y = fmaf(w1, p01.y, a1.y);
        a1.z = fmaf(w1, p01.z, a1.z); a1.w = fmaf(w1, p01.w, a1.w);
        b1.x = fmaf(w1, p11.x, b1.x); b1.y = fmaf(w1, p11.y, b1.y);
        b1.z = fmaf(w1, p11.z, b1.z); b1.w = fmaf(w1, p11.w, b1.w);
    }
    if (k < end) {
        int   c0 = __ldg(cols + k);
        float w0 = __ldg(vals + k);
        size_t f0 = (size_t)c0 * D;
        float4 p00 = __ldg((const float4*)(x0 + f0) + lane);
        float4 p10 = __ldg((const float4*)(x1 + f0) + lane);
        a0.x = fmaf(w0, p00.x, a0.x); a0.y = fmaf(w0, p00.y, a0.y);
        a0.z = fmaf(w0, p00.z, a0.z); a0.w = fmaf(w0, p00.w, a0.w);
        b0.x = fmaf(w0, p10.x, b0.x); b0.y = fmaf(w0, p10.y, b0.y);
        b0.z = fmaf(w0, p10.z, b0.z); b0.w = fmaf(w0, p10.w, b0.w);
    }
    a0.x += a1.x; a0.y += a1.y; a0.z += a1.z; a0.w += a1.w;
    b0.x += b1.x; b0.y += b1.y; b0.z += b1.z; b0.w += b1.w;
    size_t obase = (size_t)(row + row_off) * D;
    ((float4*)(o0 + obase))[lane] = a0;
    ((float4*)(o1 + obase))[lane] = b0;
}

__global__ void spmm1_kernel(const int* __restrict__ rowptr,
                             const int* __restrict__ cols,
                             const float* __restrict__ vals,
                             const float* __restrict__ x,
                             float* __restrict__ o,
                             float* __restrict__ cge,
                             int mode, int n_rows) {
    spmm1_device(rowptr, cols, vals, x, o, cge, mode, n_rows, 0, blockIdx.x);
}

// ---------------- conflict-free FFMA2 GEMM ------------------
#define GM_BM 64
#define GM_BN 64
#define GM_BK 16
#define MBLK  469   // ceil(30000 / 64)

struct GemmJob {
    const float* A; const float* A2; const float* B;
    const float* bias; const float* F;
    float* out; int M; int K; int mode; int splits;
};

__device__ void gemm_device(const GemmJob j, int local) {
    __shared__ float As[GM_BK][GM_BM];     // 4KB, transposed A
    __shared__ float Bs[GM_BK * GM_BN];    // 4KB, linear [k*64 + n]

    int split = local / MBLK;
    int mblk  = local % MBLK;
    int Kc    = j.K / j.splits;
    int kbeg  = split * Kc;
    int kend  = kbeg + Kc;

    int tid = threadIdx.x;
    int tx = tid & 15;
    int ty = tid >> 4;
    int m0 = mblk * GM_BM;

    int a_row = tid >> 1;
    int a_koff = (tid & 1) * 8;
    int a_gr = m0 + a_row;
    int b_half = tid >> 6;
    int b_c = tid & 63;

    unsigned long long acc[4][4];
    #pragma unroll
    for (int r = 0; r < 4; r++)
        #pragma unroll
        for (int c = 0; c < 4; c++) acc[r][c] = 0ull;

    for (int k0 = kbeg; k0 < kend; k0 += GM_BK) {
        {
            const float* arow  = j.A + (size_t)a_gr * j.K + k0 + a_koff;
            float4 av0 = make_float4(0.f,0.f,0.f,0.f);
            float4 av1 = make_float4(0.f,0.f,0.f,0.f);
            if (a_gr < j.M) {
                av0 = *(const float4*)(arow);
                av1 = *(const float4*)(arow + 4);
                if (j.A2) {
                    const float* arow2 = j.A2 + (size_t)a_gr * j.K + k0 + a_koff;
                    float4 b0 = *(const float4*)(arow2);
                    float4 b1 = *(const float4*)(arow2 + 4);
                    av0.x -= b0.x; av0.y -= b0.y; av0.z -= b0.z; av0.w -= b0.w;
                    av1.x -= b1.x; av1.y -= b1.y; av1.z -= b1.z; av1.w -= b1.w;
                }
            }
            As[a_koff + 0][a_row] = av0.x;
            As[a_koff + 1][a_row] = av0.y;
            As[a_koff + 2][a_row] = av0.z;
            As[a_koff + 3][a_row] = av0.w;
            As[a_koff + 4][a_row] = av1.x;
            As[a_koff + 5][a_row] = av1.y;
            As[a_koff + 6][a_row] = av1.z;
            As[a_koff + 7][a_row] = av1.w;
        }
        {
            #pragma unroll
            for (int i = 0; i < 8; i++) {
                int kr = 2 * i + b_half;
                Bs[i * 128 + tid] = __ldg(j.B + (size_t)(k0 + kr) * GM_BN + b_c);
            }
        }
        __syncthreads();

        #pragma unroll
        for (int kk = 0; kk < GM_BK; kk++) {
            ulonglong2 a01 = *(const ulonglong2*)&As[kk][ty * 8 + 0];
            ulonglong2 a23 = *(const ulonglong2*)&As[kk][ty * 8 + 4];
            float bs0 = Bs[kk * 64 + tx];
            float bs1 = Bs[kk * 64 + tx + 16];
            float bs2 = Bs[kk * 64 + tx + 32];
            float bs3 = Bs[kk * 64 + tx + 48];
            unsigned long long ar[4] = {a01.x, a01.y, a23.x, a23.y};
            unsigned long long bc[4] = {pack2_(bs0, bs0), pack2_(bs1, bs1),
                                        pack2_(bs2, bs2), pack2_(bs3, bs3)};
            #pragma unroll
            for (int r = 0; r < 4; r++)
                #pragma unroll
                for (int c = 0; c < 4; c++)
                    acc[r][c] = fma2_(ar[r], bc[c], acc[r][c]);
        }
        __syncthreads();
    }

    #pragma unroll
    for (int rp = 0; rp < 4; rp++) {
        int gm0 = m0 + ty * 8 + rp * 2;
        bool ok0 = gm0 < j.M, ok1 = gm0 + 1 < j.M;
        #pragma unroll
        for (int c = 0; c < 4; c++) {
            float2 p = unpack2_(acc[rp][c]);
            int gn = tx + 16 * c;
            float v0 = p.x, v1 = p.y;
            if (j.mode == 1) {
                float bs = __ldg(j.bias + gn);
                if (ok0) v0 = sigmoidf_(v0 + bs) * __ldg(j.F + (size_t)gm0 * 64 + gn);
                if (ok1) v1 = sigmoidf_(v1 + bs) * __ldg(j.F + (size_t)(gm0 + 1) * 64 + gn);
            }
            if (j.mode == 2) {
                if (ok0) red_add_f(j.out + (size_t)gm0 * 64 + gn, v0);
                if (ok1) red_add_f(j.out + (size_t)(gm0 + 1) * 64 + gn, v1);
            } else {
                if (ok0) j.out[(size_t)gm0 * 64 + gn] = v0;
                if (ok1) j.out[(size_t)(gm0 + 1) * 64 + gn] = v1;
            }
        }
    }
}

__global__ void __launch_bounds__(128) gemm1_kernel(GemmJob j) {
    gemm_device(j, blockIdx.x);
}

// ---------------- adjacency 4-channel SpMM ----------------
__global__ void spmm4_kernel(const int* __restrict__ rowptr,
                             const int* __restrict__ cols,
                             const float* __restrict__ vals,
                             const float* __restrict__ x0, const float* __restrict__ x1,
                             const float* __restrict__ x2, const float* __restrict__ x3,
                             float* __restrict__ o0, float* __restrict__ o1,
                             float* __restrict__ o2, float* __restrict__ o3,
                             int n_rows) {
    int t = blockIdx.x * blockDim.x + threadIdx.x;
    int row = t >> 4, lane = t & 15;
    if (row >= n_rows) return;
    int start = __ldg(rowptr + row), end = __ldg(rowptr + row + 1);
    float4 a0 = make_float4(0.f,0.f,0.f,0.f);
    float4 a1 = make_float4(0.f,0.f,0.f,0.f);
    float4 a2 = make_float4(0.f,0.f,0.f,0.f);
    float4 a3 = make_float4(0.f,0.f,0.f,0.f);
    for (int k = start; k < end; k++) {
        int   c = __ldg(cols + k);
        float w = __ldg(vals + k);
        size_t off = (size_t)c * D;
        float4 p0 = __ldg((const float4*)(x0 + off) + lane);
        float4 p1 = __ldg((const float4*)(x1 + off) + lane);
        float4 p2 = __ldg((const float4*)(x2 + off) + lane);
        float4 p3 = __ldg((const float4*)(x3 + off) + lane);
        a0.x = fmaf(w, p0.x, a0.x); a0.y = fmaf(w, p0.y, a0.y);
        a0.z = fmaf(w, p0.z, a0.z); a0.w = fmaf(w, p0.w, a0.w);
        a1.x = fmaf(w, p1.x, a1.x); a1.y = fmaf(w, p1.y, a1.y);
        a1.z = fmaf(w, p1.z, a1.z); a1.w = fmaf(w, p1.w, a1.w);
        a2.x = fmaf(w, p2.x, a2.x); a2.y = fmaf(w, p2.y, a2.y);
        a2.z = fmaf(w, p2.z, a2.z); a2.w = fmaf(w, p2.w, a2.w);
        a3.x = fmaf(w, p3.x, a3.x); a3.y = fmaf(w, p3.y, a3.y);
        a3.z = fmaf(w, p3.z, a3.z); a3.w = fmaf(w, p3.w, a3.w);
    }
    size_t obase = (size_t)row * D;
    ((float4*)(o0 + obase))[lane] = a0;
    ((float4*)(o1 + obase))[lane] = a1;
    ((float4*)(o2 + obase))[lane] = a2;
    ((float4*)(o3 + obase))[lane] = a3;
}

// ---------------- modal halves: ii jobs (3) and uu jobs (3) -------------------
#define JOB_BLOCKS 1875
__global__ void modal_ii_kernel(const int* __restrict__ rowptr,
                                const int* __restrict__ colss,
                                const float* __restrict__ valss,
                                const float* __restrict__ persv, const float* __restrict__ perst,
                                const float* __restrict__ comv, const float* __restrict__ comt,
                                float* __restrict__ pev, float* __restrict__ pet,
                                float* __restrict__ cev, float* __restrict__ cet) {
    int b = blockIdx.x;
    int job = b / JOB_BLOCKS;
    int lb = b % JOB_BLOCKS;
    switch (job) {
    case 0: spmm1_device(rowptr + RPO_IMG_II, colss + SEG_IMG_II, valss + SEG_IMG_II,
                         persv, pev, nullptr, 0, N_ITEMS, N_USERS, lb); break;
    case 1: spmm1_device(rowptr + RPO_TXT_II, colss + SEG_TXT_II, valss + SEG_TXT_II,
                         perst, pet, nullptr, 0, N_ITEMS, N_USERS, lb); break;
    default: spmm2_device(rowptr + RPO_CII, colss + SEG_CII, valss + SEG_CII,
                         comv, comt, cev, cet, N_ITEMS, N_USERS, lb); break;
    }
}

__global__ void modal_uu_kernel(const int* __restrict__ rowptr,
                                const int* __restrict__ colss,
                                const float* __restrict__ valss,
                                const float* __restrict__ upv, const float* __restrict__ upt,
                                const float* __restrict__ ucv, const float* __restrict__ uct,
                                float* __restrict__ pev, float* __restrict__ pet,
                                float* __restrict__ cev, float* __restrict__ cet) {
    int b = blockIdx.x;
    int job = b / JOB_BLOCKS;
    int lb = b % JOB_BLOCKS;
    switch (job) {
    case 0: spmm1_device(rowptr + RPO_IMG_UU, colss + SEG_IMG_UU, valss + SEG_IMG_UU,
                         upv, pev, nullptr, 0, N_USERS, 0, lb); break;
    case 1: spmm1_device(rowptr + RPO_TXT_UU, colss + SEG_TXT_UU, valss + SEG_TXT_UU,
                         upt, pet, nullptr, 0, N_USERS, 0, lb); break;
    default: spmm2_device(rowptr + RPO_CUU, colss + SEG_CUU, valss + SEG_CUU,
                         ucv, uct, cev, cet, N_USERS, 0, lb); break;
    }
}

// ---------------- final ----------------
__global__ void final_kernel(const float* __restrict__ cge,
                             const float* __restrict__ pev,
                             const float* __restrict__ pet,
                             const float* __restrict__ cev,
                             const float* __restrict__ cet,
                             const float* __restrict__ att,
                             float* __restrict__ out) {
    int warp = (blockIdx.x * blockDim.x + threadIdx.x) >> 5;
    int lane = threadIdx.x & 31;
    if (warp >= N_NODES) return;
    float a0 = __ldg(att + 0), a1 = __ldg(att + 1);
    float mx = fmaxf(a0, a1);
    float e0 = __expf(a0 - mx), e1 = __expf(a1 - mx);
    float inv = 1.0f / (e0 + e1);
    float w0 = e0 * inv, w1 = e1 * inv;

    size_t base = (size_t)warp * D;
    float p0 = w0 * pev[base + lane]      + w1 * pet[base + lane];
    float p1 = w0 * pev[base + 32 + lane] + w1 * pet[base + 32 + lane];
    float c0 = w0 * cev[base + lane]      + w1 * cet[base + lane];
    float c1 = w0 * cev[base + 32 + lane] + w1 * cet[base + 32 + lane];

    float sp = p0 * p0 + p1 * p1;
    float sc = c0 * c0 + c1 * c1;
    #pragma unroll
    for (int o = 16; o; o >>= 1) {
        sp += __shfl_xor_sync(0xffffffffu, sp, o);
        sc += __shfl_xor_sync(0xffffffffu, sc, o);
    }
    float ip = 1.0f / (sqrtf(sp) + 1e-12f);
    float ic = 1.0f / (sqrtf(sc) + 1e-12f);
    const float third = 1.0f / 3.0f;
    out[base + lane]      = cge[base + lane] * third      + 0.3f * p0 * ip + 0.8f * c0 * ic;
    out[base + 32 + lane] = cge[base + 32 + lane] * third + 0.3f * p1 * ip + 0.8f * c1 * ic;
}

// ---------------- host ----------------
static inline unsigned gdiv(long long t, int b) { return (unsigned)((t + b - 1) / b); }

extern "C" void kernel_launch(void* const* d_in, const int* in_sizes, int n_in,
                              void* d_out, int out_size) {
    const float* user_emb    = (const float*)d_in[0];
    const float* item_emb    = (const float*)d_in[1];
    const float* image_feats = (const float*)d_in[2];
    const float* text_feats  = (const float*)d_in[3];
    const float* trs_v       = (const float*)d_in[4];
    const float* trs_t       = (const float*)d_in[5];
    const float* gate_v      = (const float*)d_in[6];
    const float* gate1_v     = (const float*)d_in[7];
    const float* gate_t      = (const float*)d_in[8];
    const float* gate1_t     = (const float*)d_in[9];
    const float* bias_v      = (const float*)d_in[10];
    const float* bias1_v     = (const float*)d_in[11];
    const float* bias_t      = (const float*)d_in[12];
    const float* bias1_t     = (const float*)d_in[13];
    const float* att         = (const float*)d_in[14];
    const float* num_inters  = (const float*)d_in[15];
    const float* vals_norm   = (const float*)d_in[16];
    const float* vals_adj    = (const float*)d_in[17];
    const float* vals_img_ii = (const float*)d_in[18];
    const float* vals_txt_ii = (const float*)d_in[19];
    const float* vals_img_uu = (const float*)d_in[20];
    const float* vals_txt_uu = (const float*)d_in[21];
    const float* vals_cii    = (const float*)d_in[22];
    const float* vals_cuu    = (const float*)d_in[23];
    const int* idx_norm      = (const int*)d_in[24];
    const int* idx_adj       = (const int*)d_in[25];
    const int* idx_img_ii    = (const int*)d_in[26];
    const int* idx_txt_ii    = (const int*)d_in[27];
    const int* idx_img_uu    = (const int*)d_in[28];
    const int* idx_txt_uu    = (const int*)d_in[29];
    const int* idx_cii       = (const int*)d_in[30];
    const int* idx_cuu       = (const int*)d_in[31];
    float* out = (float*)d_out;

    float *egoA, *egoB, *cge, *fv, *comv, *persv, *ft, *comt, *perst;
    float *upv, *ucv, *upt, *uct, *pev, *cev, *pet, *cet;
    int *counts, *rowptr, *cursor, *colss; float* valss;
    cudaGetSymbolAddress((void**)&egoA,  g_egoA);
    cudaGetSymbolAddress((void**)&egoB,  g_egoB);
    cudaGetSymbolAddress((void**)&cge,   g_cge);
    cudaGetSymbolAddress((void**)&fv,    g_fv);
    cudaGetSymbolAddress((void**)&comv,  g_comv);
    cudaGetSymbolAddress((void**)&persv, g_persv);
    cudaGetSymbolAddress((void**)&ft,    g_ft);
    cudaGetSymbolAddress((void**)&comt,  g_comt);
    cudaGetSymbolAddress((void**)&perst, g_perst);
    cudaGetSymbolAddress((void**)&upv,   g_upv);
    cudaGetSymbolAddress((void**)&ucv,   g_ucv);
    cudaGetSymbolAddress((void**)&upt,   g_upt);
    cudaGetSymbolAddress((void**)&uct,   g_uct);
    cudaGetSymbolAddress((void**)&pev,   g_pev);
    cudaGetSymbolAddress((void**)&cev,   g_cev);
    cudaGetSymbolAddress((void**)&pet,   g_pet);
    cudaGetSymbolAddress((void**)&cet,   g_cet);
    cudaGetSymbolAddress((void**)&counts, g_counts);
    cudaGetSymbolAddress((void**)&rowptr, g_rowptr);
    cudaGetSymbolAddress((void**)&cursor, g_cursor);
    cudaGetSymbolAddress((void**)&colss,  g_colss);
    cudaGetSymbolAddress((void**)&valss,  g_valss);

    // streams + events (handles only; created once)
    static cudaStream_t s2 = nullptr, s3 = nullptr;
    static cudaEvent_t evFork = nullptr, evScatter = nullptr;
    static cudaEvent_t evG1v = nullptr, evG1t = nullptr, evSp4 = nullptr;
    if (!s2) {
        cudaStreamCreateWithFlags(&s2, cudaStreamNonBlocking);
        cudaStreamCreateWithFlags(&s3, cudaStreamNonBlocking);
        cudaEventCreateWithFlags(&evFork,    cudaEventDisableTiming);
        cudaEventCreateWithFlags(&evScatter, cudaEventDisableTiming);
        cudaEventCreateWithFlags(&evG1v,     cudaEventDisableTiming);
        cudaEventCreateWithFlags(&evG1t,     cudaEventDisableTiming);
        cudaEventCreateWithFlags(&evSp4,     cudaEventDisableTiming);
    }

    // ---- stream 0: shared memsets, then fork ----
    cudaMemsetAsync(counts, 0, RP_TOTAL * sizeof(int), 0);
    const size_t FB = (size_t)N_ITEMS * D * sizeof(float);
    cudaMemsetAsync(fv, 0, FB, 0);
    cudaMemsetAsync(ft, 0, FB, 0);
    cudaEventRecord(evFork, 0);

    // ---- chain B-img (s2): img GEMM -> gate_v -> gate1_v ----
    cudaStreamWaitEvent(s2, evFork, 0);
    GemmJob jImg  = { image_feats, nullptr, trs_v,   nullptr,  nullptr, fv,    N_ITEMS, IMG_DIM, 2, 4 };
    GemmJob jGv   = { fv,          nullptr, gate_v,  bias_v,   fv,      comv,  N_ITEMS, 64,      1, 1 };
    GemmJob jG1v  = { fv,          comv,    gate1_v, bias1_v,  fv,      persv, N_ITEMS, 64,      1, 1 };
    gemm1_kernel<<<MBLK * 4, 128, 0, s2>>>(jImg);
    gemm1_kernel<<<MBLK, 128, 0, s2>>>(jGv);
    gemm1_kernel<<<MBLK, 128, 0, s2>>>(jG1v);
    cudaEventRecord(evG1v, s2);

    // ---- chain B-txt (s3): txt GEMM -> gate_t -> gate1_t ----
    cudaStreamWaitEvent(s3, evFork, 0);
    GemmJob jTxt  = { text_feats,  nullptr, trs_t,   nullptr,  nullptr, ft,    N_ITEMS, TXT_DIM, 2, 2 };
    GemmJob jGt   = { ft,          nullptr, gate_t,  bias_t,   ft,      comt,  N_ITEMS, 64,      1, 1 };
    GemmJob jG1t  = { ft,          comt,    gate1_t, bias1_t,  ft,      perst, N_ITEMS, 64,      1, 1 };
    gemm1_kernel<<<MBLK * 2, 128, 0, s3>>>(jTxt);
    gemm1_kernel<<<MBLK, 128, 0, s3>>>(jGt);
    gemm1_kernel<<<MBLK, 128, 0, s3>>>(jG1t);
    cudaEventRecord(evG1t, s3);

    // ---- chain A (stream 0): CSR build + norm propagation ----
    build1_kernel<<<HIST_BLOCKS + CAT_BLOCKS, 256>>>(
        idx_norm, idx_adj, idx_img_ii, idx_txt_ii, idx_img_uu, idx_txt_uu, idx_cii, idx_cuu,
        counts, user_emb, item_emb, egoA);
    scan_kernel<<<8, 1024>>>(counts, rowptr);
    cudaMemcpyAsync(cursor, rowptr, RP_TOTAL * sizeof(int), cudaMemcpyDeviceToDevice, 0);
    scatter_kernel<<<gdiv(NNZ_TOT, 256), 256>>>(idx_norm, idx_adj, idx_img_ii, idx_txt_ii,
                                                idx_img_uu, idx_txt_uu, idx_cii, idx_cuu,
                                                vals_norm, vals_adj, vals_img_ii, vals_txt_ii,
                                                vals_img_uu, vals_txt_uu, vals_cii, vals_cuu,
                                                num_inters, cursor, colss, valss);
    cudaEventRecord(evScatter, 0);

    // spmm4 on s2: needs gates1 of both modalities + scatter
    cudaStreamWaitEvent(s2, evScatter, 0);
    cudaStreamWaitEvent(s2, evG1t, 0);
    unsigned gusers = gdiv((long long)N_USERS * 16, 256);
    spmm4_kernel<<<gusers, 256, 0, s2>>>(rowptr + RPO_ADJ, colss + SEG_ADJ, valss + SEG_ADJ,
                                         persv, comv, perst, comt,
                                         upv, ucv, upt, uct, N_USERS);
    cudaEventRecord(evSp4, s2);

    // ---- chain A continues: norm layers ----
    const int* rpN = rowptr + RPO_NORM;
    const int* clN = colss + SEG_NORM;
    const float* vlN = valss + SEG_NORM;
    unsigned gnodes = gdiv((long long)N_NODES * 16, 256);
    spmm1_kernel<<<gnodes, 256>>>(rpN, clN, vlN, egoA, egoB, cge, 1, N_NODES);
    spmm1_kernel<<<gnodes, 256>>>(rpN, clN, vlN, egoB, egoA, cge, 2, N_NODES);
    spmm1_kernel<<<gnodes, 256>>>(rpN, clN, vlN, egoA, egoB, cge, 2, N_NODES);

    // ---- modal-ii on stream 0 (needs gates1 of both) -- overlaps s2's spmm4 ----
    cudaStreamWaitEvent(0, evG1v, 0);
    cudaStreamWaitEvent(0, evG1t, 0);
    modal_ii_kernel<<<3 * JOB_BLOCKS, 256>>>(rowptr, colss, valss,
                                             persv, perst, comv, comt,
                                             pev, pet, cev, cet);

    // ---- modal-uu (needs spmm4) then final ----
    cudaStreamWaitEvent(0, evSp4, 0);
    modal_uu_kernel<<<3 * JOB_BLOCKS, 256>>>(rowptr, colss, valss,
                                             upv, upt, ucv, uct,
                                             pev, pet, cev, cet);

    final_kernel<<<gdiv((long long)N_NODES * 32, 256), 256>>>(cge, pev, pet, cev, cet, att, out);
}